// round 10
// baseline (speedup 1.0000x reference)
#include <cuda_runtime.h>
#include <cuda_bf16.h>
#include <cstdint>

// ---------------------------------------------------------------------------
//   y   = W @ x + b   (oc=128, cin=128, vox=186624)
//   out = leaky_0.2( y * (y + att[c,l,pp]/nz[c,l] + 1) )
// GEMM on mma.sync m16n8k16 (bf16) via 3-way split: Wh*xh + Wh*xl + Wl*xh
// R10: 2 persistent CTAs/SM, CTA = 128 oc x 64 vox, warp tile 32x32
//      (minimal ldmatrix traffic), single-buffered x + register prefetch.
// ---------------------------------------------------------------------------

#define CIN    128
#define COUT   128
#define HWDIM  5184
#define NVOX   186624
#define PATCH  9
#define PPSQ   81
#define NW     576
#define LPATCH 2304

#define TILE_V  64
#define NT64    2916          // NVOX / 64
#define GRID    296           // 2 CTAs per SM
#define THREADS 256

// per-CTA dynamic smem (bytes):
//   xh 16KB @0, xl 16KB @16384, Wh 32KB @32768, Wl 32KB @65536
#define SM_XH 0
#define SM_XL 16384
#define SM_W  32768
#define SMEM_TOTAL 98304      // 96KB -> 2 CTAs/SM

__device__ __align__(16) unsigned short g_Wsw[32768];   // [Wh][Wl], swizzled
__device__ __align__(16) unsigned short g_atts[COUT * LPATCH * PPSQ]; // bf16 att/nz

// ---------------------------------------------------------------------------
// helpers
// ---------------------------------------------------------------------------
__device__ __forceinline__ uint32_t smem_u32(const void* p) {
    uint32_t a;
    asm("{ .reg .u64 t; cvta.to.shared.u64 t, %1; cvt.u32.u64 %0, t; }"
        : "=r"(a) : "l"(p));
    return a;
}
__device__ __forceinline__ uint32_t pack_bf16x2(float lo, float hi) {
    uint32_t r;
    asm("cvt.rn.bf16x2.f32 %0, %1, %2;" : "=r"(r) : "f"(hi), "f"(lo));
    return r;
}
__device__ __forceinline__ int redux_add(int v) {
    int r;
    asm("redux.sync.add.s32 %0, %1, 0xffffffff;" : "=r"(r) : "r"(v));
    return r;
}
__device__ __forceinline__ void sts64(uint32_t addr, uint32_t a, uint32_t b) {
    asm volatile("st.shared.v2.u32 [%0], {%1, %2};"
                 :: "r"(addr), "r"(a), "r"(b) : "memory");
}
__device__ __forceinline__ void ldsm_x4(uint32_t addr, uint32_t* r) {
    asm volatile("ldmatrix.sync.aligned.m8n8.x4.shared.b16 {%0,%1,%2,%3}, [%4];"
                 : "=r"(r[0]), "=r"(r[1]), "=r"(r[2]), "=r"(r[3]) : "r"(addr));
}
__device__ __forceinline__ void ldsm_x4_t(uint32_t addr, uint32_t* r) {
    asm volatile("ldmatrix.sync.aligned.m8n8.x4.trans.shared.b16 {%0,%1,%2,%3}, [%4];"
                 : "=r"(r[0]), "=r"(r[1]), "=r"(r[2]), "=r"(r[3]) : "r"(addr));
}
__device__ __forceinline__ void mma16816(float* d, const uint32_t* a,
                                         uint32_t b0, uint32_t b1) {
    asm volatile(
        "mma.sync.aligned.m16n8k16.row.col.f32.bf16.bf16.f32 "
        "{%0,%1,%2,%3}, {%4,%5,%6,%7}, {%8,%9}, {%0,%1,%2,%3};"
        : "+f"(d[0]), "+f"(d[1]), "+f"(d[2]), "+f"(d[3])
        : "r"(a[0]), "r"(a[1]), "r"(a[2]), "r"(a[3]), "r"(b0), "r"(b1));
}
__device__ __forceinline__ unsigned short ldg_u16(const unsigned short* p) {
    unsigned short v;
    asm volatile("ld.global.nc.u16 %0, [%1];" : "=h"(v) : "l"(p));
    return v;
}
__device__ __forceinline__ float bf2f(unsigned short v) {
    return __uint_as_float((uint32_t)v << 16);
}
__device__ __forceinline__ float sel4(int r, float a, float b, float c, float d) {
    float v = a;
    v = (r == 1) ? b : v;
    v = (r == 2) ? c : v;
    v = (r == 3) ? d : v;
    return v;
}
// W-tile swizzle (256B rows, verified)
__device__ __forceinline__ uint32_t swz(int row, uint32_t colbyte) {
    return (uint32_t)row * 256u + (colbyte ^ (uint32_t)((row & 7) << 4));
}

// ---------------------------------------------------------------------------
// Prep: W bf16 hi/lo split (swizzled) + att -> bf16(att/nz) into g_atts.
// (verified R7/R9 code)
// ---------------------------------------------------------------------------
__device__ __forceinline__ void process_group(const float4* f, int g, int lane)
{
    int c0 = 0, c1 = 0, c2 = 0, c3 = 0;
#pragma unroll
    for (int p = 0; p < 3; p++) {
        int idx = p * 32 + lane;
        if (idx < 81) {
            float4 q = f[p];
            int e = idx * 4;
            int r0 = (e >= 81) + (e >= 162) + (e >= 243);
            int r3 = (e + 3 >= 81) + (e + 3 >= 162) + (e + 3 >= 243);
            if (r0 == r3) {
                int cnt = (q.x != 0.f) + (q.y != 0.f) + (q.z != 0.f) + (q.w != 0.f);
                c0 += (r0 == 0) ? cnt : 0;
                c1 += (r0 == 1) ? cnt : 0;
                c2 += (r0 == 2) ? cnt : 0;
                c3 += (r0 == 3) ? cnt : 0;
            } else {
                float vv[4] = { q.x, q.y, q.z, q.w };
#pragma unroll
                for (int j = 0; j < 4; j++) {
                    int ej = e + j;
                    int rj = (ej >= 81) + (ej >= 162) + (ej >= 243);
                    int nz = (vv[j] != 0.f);
                    c0 += (rj == 0) ? nz : 0;
                    c1 += (rj == 1) ? nz : 0;
                    c2 += (rj == 2) ? nz : 0;
                    c3 += (rj == 3) ? nz : 0;
                }
            }
        }
    }
    c0 = redux_add(c0); c1 = redux_add(c1);
    c2 = redux_add(c2); c3 = redux_add(c3);
    float i0 = 1.0f / ((float)c0 + 1e-5f);
    float i1 = 1.0f / ((float)c1 + 1e-5f);
    float i2 = 1.0f / ((float)c2 + 1e-5f);
    float i3 = 1.0f / ((float)c3 + 1e-5f);

#pragma unroll
    for (int p = 0; p < 3; p++) {
        int idx = p * 32 + lane;
        if (idx < 81) {
            float4 q = f[p];
            int e = idx * 4;
            int r0 = (e >= 81) + (e >= 162) + (e >= 243);
            int r1 = (e + 1 >= 81) + (e + 1 >= 162) + (e + 1 >= 243);
            int r2 = (e + 2 >= 81) + (e + 2 >= 162) + (e + 2 >= 243);
            int r3 = (e + 3 >= 81) + (e + 3 >= 162) + (e + 3 >= 243);
            float s0 = sel4(r0, i0, i1, i2, i3);
            float s1 = sel4(r1, i0, i1, i2, i3);
            float s2 = sel4(r2, i0, i1, i2, i3);
            float s3 = sel4(r3, i0, i1, i2, i3);
            uint32_t u01 = pack_bf16x2(q.x * s0, q.y * s1);
            uint32_t u23 = pack_bf16x2(q.z * s2, q.w * s3);
            *(uint2*)(g_atts + (size_t)g * 324 + idx * 4) = make_uint2(u01, u23);
        }
    }
}

__global__ __launch_bounds__(256) void prep_kernel(const float* __restrict__ att,
                                                   const float* __restrict__ W)
{
    const int tid = threadIdx.x;
    const int blk = blockIdx.x;

    if (blk < 64) {   // W split
        int idx = blk * 256 + tid;
        int oc = idx >> 7, k = idx & 127;
        float w = W[idx];
        __nv_bfloat16 h = __float2bfloat16(w);
        float hf = __bfloat162float(h);
        __nv_bfloat16 l = __float2bfloat16(w - hf);
        uint32_t off = swz(oc, (uint32_t)(k * 2)) >> 1;
        g_Wsw[off]         = *(unsigned short*)&h;
        g_Wsw[off + 16384] = *(unsigned short*)&l;
    }

    const int wg = (blk * 256 + tid) >> 5;
    const int lane = tid & 31;
    const int g0 = wg * 2;
    const float4* a4a = (const float4*)att + (size_t)g0 * 81;
    const float4* a4b = a4a + 81;

    float4 fa[3], fb[3];
#pragma unroll
    for (int p = 0; p < 3; p++) {
        int idx = p * 32 + lane;
        if (idx < 81) {
            fa[p] = __ldg(a4a + idx);
            fb[p] = __ldg(a4b + idx);
        }
    }
    process_group(fa, g0, lane);
    process_group(fb, g0 + 1, lane);
}

// ---------------------------------------------------------------------------
// Fused persistent kernel: CTA = 128 oc x 64 vox, 8 warps (4 oc x 2 vox),
// warp tile 32 oc x 32 vox, single-buffered x, 2 CTAs/SM.
// ---------------------------------------------------------------------------
struct XFrag { float4 f[8]; };

// warp wid loads k rows [wid*16, wid*16+16) of the 64-vox tile (verified R9)
__device__ __forceinline__ void ldg_tile(const float* __restrict__ x,
                                         int v0, int wid, int lane, XFrag& r)
{
    const int k0 = wid * 16 + (lane >> 4);
    const float* xp = x + (size_t)k0 * NVOX + v0 + (lane & 15) * 4;
#pragma unroll
    for (int i = 0; i < 8; i++)
        r.f[i] = *(const float4*)(xp + (size_t)(2 * i) * NVOX);
}

// buffer: 128 k-rows x 64 vox bf16, 128B rows, chunk xor (k&7) (verified R9)
__device__ __forceinline__ void sts_tile(uint32_t bufH, int wid, int lane,
                                         const XFrag& r)
{
    const int kbase = wid * 16 + (lane >> 4);
    const uint32_t voxb = (uint32_t)((lane & 15) * 8);
#pragma unroll
    for (int i = 0; i < 8; i++) {
        const int k = kbase + 2 * i;
        float4 f = r.f[i];
        uint32_t h01 = pack_bf16x2(f.x, f.y);
        uint32_t h23 = pack_bf16x2(f.z, f.w);
        float h0 = __uint_as_float(h01 << 16);
        float h1 = __uint_as_float(h01 & 0xffff0000u);
        float h2 = __uint_as_float(h23 << 16);
        float h3 = __uint_as_float(h23 & 0xffff0000u);
        uint32_t l01 = pack_bf16x2(f.x - h0, f.y - h1);
        uint32_t l23 = pack_bf16x2(f.z - h2, f.w - h3);
        uint32_t addr = bufH + (uint32_t)k * 128u
                      + (voxb ^ (uint32_t)((k & 7) << 4));
        sts64(addr, h01, h23);
        sts64(addr + 16384, l01, l23);   // xl 16KB after xh
    }
}

__global__ __launch_bounds__(THREADS, 2)
void fused_kernel(const float* __restrict__ x,
                  const float* __restrict__ b,
                  float* __restrict__ out)
{
    extern __shared__ __align__(16) char smem[];
    const uint32_t sbase = smem_u32(smem);
    const int tid  = threadIdx.x;
    const int lane = tid & 31;
    const int wid  = tid >> 5;              // 0..7

    // --- load full W once (64KB) ---
    {
        const float4* Wv = (const float4*)g_Wsw;
        float4* sWv = (float4*)(smem + SM_W);
#pragma unroll
        for (int i = 0; i < 16; i++)
            sWv[tid + THREADS * i] = Wv[tid + THREADS * i];
    }

    const int ocb = (wid & 3) * 32;         // oc group (32 oc per warp)
    const int vh  = (wid >> 2) * 32;        // vox group within 64
    const int ocl = ocb + (lane >> 2);

    // A-side ldmatrix ([oc][k] 256B rows, verified R7)
    const int aRow = ocb + (lane & 15);
    const uint32_t aSw = (uint32_t)((aRow & 7) << 4);
    const uint32_t aK  = (uint32_t)((lane >> 4) * 16);
    const uint32_t aB  = sbase + SM_W + (uint32_t)aRow * 256u;

    // B-side ldmatrix.trans (128B rows, xor (k&7), verified R9)
    const int bK = lane & 15;
    uint32_t bOff[2];
#pragma unroll
    for (int nbp = 0; nbp < 2; nbp++) {
        uint32_t voxbyte = (uint32_t)(vh * 2 + nbp * 32 + (lane >> 4) * 16);
        bOff[nbp] = (uint32_t)bK * 128u
                  + (voxbyte ^ ((uint32_t)(bK & 7) << 4));
    }

    const float bias0a = __ldg(b + ocl);
    const float bias0b = __ldg(b + ocl + 8);
    const float bias1a = __ldg(b + ocl + 16);
    const float bias1b = __ldg(b + ocl + 24);

    // prologue: tile0 into the single buffer
    int t = blockIdx.x;
    {
        XFrag r0;
        ldg_tile(x, t * TILE_V, wid, lane, r0);
        sts_tile(sbase + SM_XH, wid, lane, r0);
    }
    __syncthreads();

    while (true) {
        const int tn = t + GRID;
        const bool has_next = (tn < NT64);

        // prefetch next x tile into regs (hidden under MMA)
        XFrag rn;
        if (has_next) ldg_tile(x, tn * TILE_V, wid, lane, rn);

        // prefetch epilogue att values for tile t (verified R7)
        unsigned short avr[2][4][4];
        {
            int l0x[4], p0x[4], l1x[4], p1x[4];
#pragma unroll
            for (int nb = 0; nb < 4; nb++) {
                int v  = t * TILE_V + vh + 2 * (lane & 3) + nb * 8;
                int d  = v / HWDIM;
                int hw = v - d * HWDIM;
                int id = d / PATCH,  pd = d  - id * PATCH;
                int iw = hw / PATCH, pw = hw - iw * PATCH;
                int l0 = id * NW + iw, p0 = pd * PATCH + pw;
                l0x[nb] = l0; p0x[nb] = p0;
                if (pw == PATCH - 1) { l1x[nb] = l0 + 1; p1x[nb] = pd * PATCH; }
                else                 { l1x[nb] = l0;     p1x[nb] = p0 + 1; }
            }
#pragma unroll
            for (int tt = 0; tt < 2; tt++) {
                const unsigned short* A0 =
                    g_atts + (size_t)(ocl + 16 * tt) * (LPATCH * PPSQ);
                const unsigned short* A1 = A0 + (size_t)8 * (LPATCH * PPSQ);
#pragma unroll
                for (int nb = 0; nb < 4; nb++) {
                    avr[tt][nb][0] = ldg_u16(A0 + l0x[nb] * PPSQ + p0x[nb]);
                    avr[tt][nb][1] = ldg_u16(A0 + l1x[nb] * PPSQ + p1x[nb]);
                    avr[tt][nb][2] = ldg_u16(A1 + l0x[nb] * PPSQ + p0x[nb]);
                    avr[tt][nb][3] = ldg_u16(A1 + l1x[nb] * PPSQ + p1x[nb]);
                }
            }
        }

        // accumulators, init with bias
        float acc[2][4][4];
#pragma unroll
        for (int nb = 0; nb < 4; nb++) {
            acc[0][nb][0] = bias0a; acc[0][nb][1] = bias0a;
            acc[0][nb][2] = bias0b; acc[0][nb][3] = bias0b;
            acc[1][nb][0] = bias1a; acc[1][nb][1] = bias1a;
            acc[1][nb][2] = bias1b; acc[1][nb][3] = bias1b;
        }

        // MMA over 8 k-steps, 3 split terms (verified R7 inner loop)
        const uint32_t bufH = sbase + SM_XH;
        const uint32_t bufL = sbase + SM_XL;
#pragma unroll
        for (int ks = 0; ks < 8; ks++) {
            const uint32_t kbA = ((uint32_t)(ks * 32) + aK) ^ aSw;
            uint32_t a0h[4], a1h[4], a0l[4], a1l[4];
            ldsm_x4(aB + kbA,                a0h);
            ldsm_x4(aB + 4096 + kbA,         a1h);
            ldsm_x4(aB + 32768 + kbA,        a0l);
            ldsm_x4(aB + 32768 + 4096 + kbA, a1l);

            const uint32_t krow = (uint32_t)(ks * 2048);   // 16 rows x 128B
#pragma unroll
            for (int nbp = 0; nbp < 2; nbp++) {
                uint32_t bh[4], bl[4];
                ldsm_x4_t(bufH + krow + bOff[nbp], bh);
                ldsm_x4_t(bufL + krow + bOff[nbp], bl);
                float* A00 = acc[0][2 * nbp];
                float* A10 = acc[1][2 * nbp];
                float* A01 = acc[0][2 * nbp + 1];
                float* A11 = acc[1][2 * nbp + 1];
                mma16816(A00, a0h, bh[0], bh[1]);
                mma16816(A10, a1h, bh[0], bh[1]);
                mma16816(A01, a0h, bh[2], bh[3]);
                mma16816(A11, a1h, bh[2], bh[3]);
                mma16816(A00, a0h, bl[0], bl[1]);
                mma16816(A10, a1h, bl[0], bl[1]);
                mma16816(A01, a0h, bl[2], bl[3]);
                mma16816(A11, a1h, bl[2], bl[3]);
                mma16816(A00, a0l, bh[0], bh[1]);
                mma16816(A10, a1l, bh[0], bh[1]);
                mma16816(A01, a0l, bh[2], bh[3]);
                mma16816(A11, a1l, bh[2], bh[3]);
            }
        }

        __syncthreads();   // all warps done reading the buffer

        // refill the single buffer with the next tile
        if (has_next) sts_tile(sbase + SM_XH, wid, lane, rn);

        // epilogue: regs + STG only (overlaps STS drain; other CTA fills pipe)
        const int voxbase = t * TILE_V + vh + 2 * (lane & 3);
#pragma unroll
        for (int tt = 0; tt < 2; tt++) {
            float* o0 = out + (size_t)(ocl + 16 * tt) * NVOX;
            float* o1 = o0 + (size_t)8 * NVOX;
#pragma unroll
            for (int nb = 0; nb < 4; nb++) {
                const int v = voxbase + nb * 8;
                float a00 = bf2f(avr[tt][nb][0]);
                float a01 = bf2f(avr[tt][nb][1]);
                float a10 = bf2f(avr[tt][nb][2]);
                float a11 = bf2f(avr[tt][nb][3]);

                float y;
                float2 r;
                y = acc[tt][nb][0]; r.x = y * (y + a00 + 1.0f);
                r.x = (r.x >= 0.0f) ? r.x : 0.2f * r.x;
                y = acc[tt][nb][1]; r.y = y * (y + a01 + 1.0f);
                r.y = (r.y >= 0.0f) ? r.y : 0.2f * r.y;
                *(float2*)(o0 + v) = r;

                y = acc[tt][nb][2]; r.x = y * (y + a10 + 1.0f);
                r.x = (r.x >= 0.0f) ? r.x : 0.2f * r.x;
                y = acc[tt][nb][3]; r.y = y * (y + a11 + 1.0f);
                r.y = (r.y >= 0.0f) ? r.y : 0.2f * r.y;
                *(float2*)(o1 + v) = r;
            }
        }

        if (!has_next) break;
        __syncthreads();   // buffer ready for next MMA
        t = tn;
    }
}

// ---------------------------------------------------------------------------
extern "C" void kernel_launch(void* const* d_in, const int* in_sizes, int n_in,
                              void* d_out, int out_size)
{
    (void)in_sizes; (void)n_in; (void)out_size;
    const float* x   = (const float*)d_in[0];
    const float* att = (const float*)d_in[1];
    const float* W   = (const float*)d_in[2];
    const float* b   = (const float*)d_in[3];
    float* out = (float*)d_out;

    prep_kernel<<<4608, 256>>>(att, W);

    cudaFuncSetAttribute(fused_kernel,
                         cudaFuncAttributeMaxDynamicSharedMemorySize,
                         SMEM_TOTAL);
    fused_kernel<<<GRID, THREADS, SMEM_TOTAL>>>(x, b, out);
}

// round 11
// speedup vs baseline: 1.0999x; 1.0999x over previous
#include <cuda_runtime.h>
#include <cuda_bf16.h>
#include <cstdint>

// ---------------------------------------------------------------------------
//   y   = W @ x + b   (oc=128, cin=128, vox=186624)
//   out = leaky_0.2( y * (y + att[c,l,pp]/nz[c,l] + 1) )
// GEMM on mma.sync m16n8k16 (bf16) via 3-way split: Wh*xh + Wh*xl + Wl*xh
// R11: LSU-cut round. prep pre-folds att -> voxel-major bf16 (epilogue loads
//      become 16 coalesced u32, zero index math); x staging uses STS.128.
//      Skeleton = R10 (2 persistent CTAs/SM, 128oc x 64vox, warp tile 32x32).
// ---------------------------------------------------------------------------

#define CIN    128
#define COUT   128
#define HWDIM  5184
#define NVOX   186624
#define PATCH  9
#define PPSQ   81
#define NW     576
#define LPATCH 2304

#define TILE_V  64
#define NT64    2916          // NVOX / 64
#define GRID    296           // 2 CTAs per SM
#define THREADS 256

// per-CTA dynamic smem (bytes):
//   xh 16KB @0, xl 16KB @16384, Wh 32KB @32768, Wl 32KB @65536
#define SM_XH 0
#define SM_XL 16384
#define SM_W  32768
#define SMEM_TOTAL 98304      // 96KB -> 2 CTAs/SM

__device__ __align__(16) unsigned short g_Wsw[32768];        // [Wh][Wl], swizzled
__device__ __align__(16) unsigned short g_atts2[COUT * NVOX]; // bf16 att/nz, voxel-major

// ---------------------------------------------------------------------------
// helpers
// ---------------------------------------------------------------------------
__device__ __forceinline__ uint32_t smem_u32(const void* p) {
    uint32_t a;
    asm("{ .reg .u64 t; cvta.to.shared.u64 t, %1; cvt.u32.u64 %0, t; }"
        : "=r"(a) : "l"(p));
    return a;
}
__device__ __forceinline__ uint32_t pack_bf16x2(float lo, float hi) {
    uint32_t r;
    asm("cvt.rn.bf16x2.f32 %0, %1, %2;" : "=r"(r) : "f"(hi), "f"(lo));
    return r;
}
__device__ __forceinline__ int redux_add(int v) {
    int r;
    asm("redux.sync.add.s32 %0, %1, 0xffffffff;" : "=r"(r) : "r"(v));
    return r;
}
__device__ __forceinline__ void sts128(uint32_t addr, uint32_t a, uint32_t b,
                                       uint32_t c, uint32_t d) {
    asm volatile("st.shared.v4.u32 [%0], {%1, %2, %3, %4};"
                 :: "r"(addr), "r"(a), "r"(b), "r"(c), "r"(d) : "memory");
}
__device__ __forceinline__ void ldsm_x4(uint32_t addr, uint32_t* r) {
    asm volatile("ldmatrix.sync.aligned.m8n8.x4.shared.b16 {%0,%1,%2,%3}, [%4];"
                 : "=r"(r[0]), "=r"(r[1]), "=r"(r[2]), "=r"(r[3]) : "r"(addr));
}
__device__ __forceinline__ void ldsm_x4_t(uint32_t addr, uint32_t* r) {
    asm volatile("ldmatrix.sync.aligned.m8n8.x4.trans.shared.b16 {%0,%1,%2,%3}, [%4];"
                 : "=r"(r[0]), "=r"(r[1]), "=r"(r[2]), "=r"(r[3]) : "r"(addr));
}
__device__ __forceinline__ void mma16816(float* d, const uint32_t* a,
                                         uint32_t b0, uint32_t b1) {
    asm volatile(
        "mma.sync.aligned.m16n8k16.row.col.f32.bf16.bf16.f32 "
        "{%0,%1,%2,%3}, {%4,%5,%6,%7}, {%8,%9}, {%0,%1,%2,%3};"
        : "+f"(d[0]), "+f"(d[1]), "+f"(d[2]), "+f"(d[3])
        : "r"(a[0]), "r"(a[1]), "r"(a[2]), "r"(a[3]), "r"(b0), "r"(b1));
}
__device__ __forceinline__ uint32_t ldg_u32(const void* p) {
    uint32_t v;
    asm volatile("ld.global.nc.u32 %0, [%1];" : "=r"(v) : "l"(p));
    return v;
}
// W-tile swizzle (256B rows, verified)
__device__ __forceinline__ uint32_t swz(int row, uint32_t colbyte) {
    return (uint32_t)row * 256u + (colbyte ^ (uint32_t)((row & 7) << 4));
}

// ---------------------------------------------------------------------------
// Prep: W bf16 hi/lo split (swizzled) + att folded to voxel-major bf16(att/nz).
// CTA = (oc, id, iwb): loads 64 patch-rows (5184 floats, coalesced) to smem,
// counts nz per row locally, writes 9 output d-rows x 576 hw (coalesced u32).
// ---------------------------------------------------------------------------
__global__ __launch_bounds__(256) void prep_kernel(const float* __restrict__ att,
                                                   const float* __restrict__ W)
{
    __shared__ float srow[64 * 81];   // 20736 B
    __shared__ float sinv[64];

    const int tid = threadIdx.x;
    const int blk = blockIdx.x;

    if (blk < 64) {   // W split (verified)
        int idx = blk * 256 + tid;
        int oc = idx >> 7, k = idx & 127;
        float w = W[idx];
        __nv_bfloat16 h = __float2bfloat16(w);
        float hf = __bfloat162float(h);
        __nv_bfloat16 l = __float2bfloat16(w - hf);
        uint32_t off = swz(oc, (uint32_t)(k * 2)) >> 1;
        g_Wsw[off]         = *(unsigned short*)&h;
        g_Wsw[off + 16384] = *(unsigned short*)&l;
    }

    const int oc  = blk / 36;
    const int rem = blk - oc * 36;
    const int id  = rem / 9;
    const int iwb = rem - id * 9;

    // load 64 rows x 81 floats (contiguous slab, 16B-aligned: row idx % 4 == 0)
    {
        const float4* s4 = (const float4*)(att
            + (size_t)(oc * LPATCH + id * 576 + iwb * 64) * PPSQ);
        float4* d4 = (float4*)srow;
        for (int i = tid; i < 1296; i += 256)
            d4[i] = __ldg(s4 + i);
    }
    __syncthreads();

    // nz per row: 8 warps x 8 rows
    {
        const int w = tid >> 5, lane = tid & 31;
#pragma unroll
        for (int rr = 0; rr < 8; rr++) {
            const int r = w * 8 + rr;
            const float* p = srow + r * 81;
            int cnt = (p[lane] != 0.0f) + (p[lane + 32] != 0.0f);
            if (lane < 17) cnt += (p[lane + 64] != 0.0f);
            cnt = redux_add(cnt);
            if (lane == 0) sinv[r] = 1.0f / ((float)cnt + 1e-5f);
        }
    }
    __syncthreads();

    // write voxel-major: d = id*9+pd, hw = iwb*576 + j ; val = srow[iw][pd*9+pw]/nz
    {
        uint32_t* dst = (uint32_t*)(g_atts2
            + (size_t)oc * NVOX + (size_t)(id * 9) * HWDIM + iwb * 576);
        for (int t = tid; t < 2592; t += 256) {
            int pd = t / 288;
            int c  = t - pd * 288;          // u32 index within row
            int j0 = c * 2;
            int j1 = j0 + 1;
            int iw0 = j0 / 9, pw0 = j0 - iw0 * 9;
            int iw1 = j1 / 9, pw1 = j1 - iw1 * 9;
            float v0 = srow[iw0 * 81 + pd * 9 + pw0] * sinv[iw0];
            float v1 = srow[iw1 * 81 + pd * 9 + pw1] * sinv[iw1];
            dst[(size_t)pd * 2592 + c] = pack_bf16x2(v0, v1);
        }
    }
}

// ---------------------------------------------------------------------------
// Fused persistent kernel: CTA = 128 oc x 64 vox, 8 warps (4 oc x 2 vox),
// warp tile 32 oc x 32 vox, single-buffered x, 2 CTAs/SM.
// ---------------------------------------------------------------------------
struct XFrag { float4 f[8]; };

// thread = 4 k-rows x 8 consecutive vox: k0 = wid*16 + (lane>>3)*4, vox (lane&7)*8
__device__ __forceinline__ void ldg_tile(const float* __restrict__ x,
                                         int v0, int wid, int lane, XFrag& r)
{
    const int k0 = wid * 16 + (lane >> 3) * 4;
    const float* xp = x + (size_t)k0 * NVOX + v0 + (lane & 7) * 8;
#pragma unroll
    for (int i = 0; i < 4; i++) {
        r.f[2 * i]     = *(const float4*)(xp + (size_t)i * NVOX);
        r.f[2 * i + 1] = *(const float4*)(xp + (size_t)i * NVOX + 4);
    }
}

// buffer: 128 k-rows x 64 vox bf16, 128B rows, 16B-chunk xor (k&7); STS.128
__device__ __forceinline__ void sts_tile(uint32_t bufH, int wid, int lane,
                                         const XFrag& r)
{
    const int k0 = wid * 16 + (lane >> 3) * 4;
    const uint32_t voxb = (uint32_t)((lane & 7) * 16);
#pragma unroll
    for (int i = 0; i < 4; i++) {
        const int k = k0 + i;
        float4 fa = r.f[2 * i];
        float4 fb = r.f[2 * i + 1];
        uint32_t h0 = pack_bf16x2(fa.x, fa.y);
        uint32_t h1 = pack_bf16x2(fa.z, fa.w);
        uint32_t h2 = pack_bf16x2(fb.x, fb.y);
        uint32_t h3 = pack_bf16x2(fb.z, fb.w);
        float a0 = __uint_as_float(h0 << 16), a1 = __uint_as_float(h0 & 0xffff0000u);
        float a2 = __uint_as_float(h1 << 16), a3 = __uint_as_float(h1 & 0xffff0000u);
        float a4 = __uint_as_float(h2 << 16), a5 = __uint_as_float(h2 & 0xffff0000u);
        float a6 = __uint_as_float(h3 << 16), a7 = __uint_as_float(h3 & 0xffff0000u);
        uint32_t l0 = pack_bf16x2(fa.x - a0, fa.y - a1);
        uint32_t l1 = pack_bf16x2(fa.z - a2, fa.w - a3);
        uint32_t l2 = pack_bf16x2(fb.x - a4, fb.y - a5);
        uint32_t l3 = pack_bf16x2(fb.z - a6, fb.w - a7);
        uint32_t addr = bufH + (uint32_t)k * 128u
                      + (voxb ^ (uint32_t)((k & 7) << 4));
        sts128(addr,         h0, h1, h2, h3);
        sts128(addr + 16384, l0, l1, l2, l3);   // xl 16KB after xh
    }
}

__global__ __launch_bounds__(THREADS, 2)
void fused_kernel(const float* __restrict__ x,
                  const float* __restrict__ b,
                  float* __restrict__ out)
{
    extern __shared__ __align__(16) char smem[];
    const uint32_t sbase = smem_u32(smem);
    const int tid  = threadIdx.x;
    const int lane = tid & 31;
    const int wid  = tid >> 5;              // 0..7

    // --- load full W once (64KB) ---
    {
        const float4* Wv = (const float4*)g_Wsw;
        float4* sWv = (float4*)(smem + SM_W);
#pragma unroll
        for (int i = 0; i < 16; i++)
            sWv[tid + THREADS * i] = Wv[tid + THREADS * i];
    }

    const int ocb = (wid & 3) * 32;         // oc group (32 oc per warp)
    const int vh  = (wid >> 2) * 32;        // vox group within 64
    const int ocl = ocb + (lane >> 2);

    // A-side ldmatrix ([oc][k] 256B rows, verified)
    const int aRow = ocb + (lane & 15);
    const uint32_t aSw = (uint32_t)((aRow & 7) << 4);
    const uint32_t aK  = (uint32_t)((lane >> 4) * 16);
    const uint32_t aB  = sbase + SM_W + (uint32_t)aRow * 256u;

    // B-side ldmatrix.trans (128B rows, xor (k&7), verified)
    const int bK = lane & 15;
    uint32_t bOff[2];
#pragma unroll
    for (int nbp = 0; nbp < 2; nbp++) {
        uint32_t voxbyte = (uint32_t)(vh * 2 + nbp * 32 + (lane >> 4) * 16);
        bOff[nbp] = (uint32_t)bK * 128u
                  + (voxbyte ^ ((uint32_t)(bK & 7) << 4));
    }

    const float bias0a = __ldg(b + ocl);
    const float bias0b = __ldg(b + ocl + 8);
    const float bias1a = __ldg(b + ocl + 16);
    const float bias1b = __ldg(b + ocl + 24);

    // prologue: tile0 into the single buffer
    int t = blockIdx.x;
    {
        XFrag r0;
        ldg_tile(x, t * TILE_V, wid, lane, r0);
        sts_tile(sbase + SM_XH, wid, lane, r0);
    }
    __syncthreads();

    while (true) {
        const int tn = t + GRID;
        const bool has_next = (tn < NT64);

        // prefetch next x tile into regs (hidden under MMA)
        XFrag rn;
        if (has_next) ldg_tile(x, tn * TILE_V, wid, lane, rn);

        // prefetch epilogue att (voxel-major, coalesced u32 = (v, v+1) pair)
        uint32_t avr[2][2][4];
        {
            const int vb = t * TILE_V + vh + 2 * (lane & 3);
#pragma unroll
            for (int tt = 0; tt < 2; tt++) {
                const unsigned short* A0 =
                    g_atts2 + (size_t)(ocl + 16 * tt) * NVOX + vb;
                const unsigned short* A1 = A0 + (size_t)8 * NVOX;
#pragma unroll
                for (int nb = 0; nb < 4; nb++) {
                    avr[tt][0][nb] = ldg_u32(A0 + nb * 8);
                    avr[tt][1][nb] = ldg_u32(A1 + nb * 8);
                }
            }
        }

        // accumulators, init with bias
        float acc[2][4][4];
#pragma unroll
        for (int nb = 0; nb < 4; nb++) {
            acc[0][nb][0] = bias0a; acc[0][nb][1] = bias0a;
            acc[0][nb][2] = bias0b; acc[0][nb][3] = bias0b;
            acc[1][nb][0] = bias1a; acc[1][nb][1] = bias1a;
            acc[1][nb][2] = bias1b; acc[1][nb][3] = bias1b;
        }

        // MMA over 8 k-steps, 3 split terms (verified inner loop)
        const uint32_t bufH = sbase + SM_XH;
        const uint32_t bufL = sbase + SM_XL;
#pragma unroll
        for (int ks = 0; ks < 8; ks++) {
            const uint32_t kbA = ((uint32_t)(ks * 32) + aK) ^ aSw;
            uint32_t a0h[4], a1h[4], a0l[4], a1l[4];
            ldsm_x4(aB + kbA,                a0h);
            ldsm_x4(aB + 4096 + kbA,         a1h);
            ldsm_x4(aB + 32768 + kbA,        a0l);
            ldsm_x4(aB + 32768 + 4096 + kbA, a1l);

            const uint32_t krow = (uint32_t)(ks * 2048);   // 16 rows x 128B
#pragma unroll
            for (int nbp = 0; nbp < 2; nbp++) {
                uint32_t bh[4], bl[4];
                ldsm_x4_t(bufH + krow + bOff[nbp], bh);
                ldsm_x4_t(bufL + krow + bOff[nbp], bl);
                float* A00 = acc[0][2 * nbp];
                float* A10 = acc[1][2 * nbp];
                float* A01 = acc[0][2 * nbp + 1];
                float* A11 = acc[1][2 * nbp + 1];
                mma16816(A00, a0h, bh[0], bh[1]);
                mma16816(A10, a1h, bh[0], bh[1]);
                mma16816(A01, a0h, bh[2], bh[3]);
                mma16816(A11, a1h, bh[2], bh[3]);
                mma16816(A00, a0h, bl[0], bl[1]);
                mma16816(A10, a1h, bl[0], bl[1]);
                mma16816(A01, a0h, bl[2], bl[3]);
                mma16816(A11, a1h, bl[2], bl[3]);
                mma16816(A00, a0l, bh[0], bh[1]);
                mma16816(A10, a1l, bh[0], bh[1]);
                mma16816(A01, a0l, bh[2], bh[3]);
                mma16816(A11, a1l, bh[2], bh[3]);
            }
        }

        __syncthreads();   // all warps done reading the buffer

        // refill the single buffer with the next tile
        if (has_next) sts_tile(sbase + SM_XH, wid, lane, rn);

        // epilogue: regs + STG only
        const int voxbase = t * TILE_V + vh + 2 * (lane & 3);
#pragma unroll
        for (int tt = 0; tt < 2; tt++) {
            float* o0 = out + (size_t)(ocl + 16 * tt) * NVOX;
            float* o1 = o0 + (size_t)8 * NVOX;
#pragma unroll
            for (int nb = 0; nb < 4; nb++) {
                const int v = voxbase + nb * 8;
                uint32_t u0 = avr[tt][0][nb];
                uint32_t u1 = avr[tt][1][nb];
                float a00 = __uint_as_float(u0 << 16);
                float a01 = __uint_as_float(u0 & 0xffff0000u);
                float a10 = __uint_as_float(u1 << 16);
                float a11 = __uint_as_float(u1 & 0xffff0000u);

                float y;
                float2 r;
                y = acc[tt][nb][0]; r.x = y * (y + a00 + 1.0f);
                r.x = (r.x >= 0.0f) ? r.x : 0.2f * r.x;
                y = acc[tt][nb][1]; r.y = y * (y + a01 + 1.0f);
                r.y = (r.y >= 0.0f) ? r.y : 0.2f * r.y;
                *(float2*)(o0 + v) = r;

                y = acc[tt][nb][2]; r.x = y * (y + a10 + 1.0f);
                r.x = (r.x >= 0.0f) ? r.x : 0.2f * r.x;
                y = acc[tt][nb][3]; r.y = y * (y + a11 + 1.0f);
                r.y = (r.y >= 0.0f) ? r.y : 0.2f * r.y;
                *(float2*)(o1 + v) = r;
            }
        }

        if (!has_next) break;
        __syncthreads();   // buffer ready for next MMA
        t = tn;
    }
}

// ---------------------------------------------------------------------------
extern "C" void kernel_launch(void* const* d_in, const int* in_sizes, int n_in,
                              void* d_out, int out_size)
{
    (void)in_sizes; (void)n_in; (void)out_size;
    const float* x   = (const float*)d_in[0];
    const float* att = (const float*)d_in[1];
    const float* W   = (const float*)d_in[2];
    const float* b   = (const float*)d_in[3];
    float* out = (float*)d_out;

    // 128 oc x 4 id x 9 iw-blocks = 4608 CTAs; first 64 also split W
    prep_kernel<<<4608, 256>>>(att, W);

    cudaFuncSetAttribute(fused_kernel,
                         cudaFuncAttributeMaxDynamicSharedMemorySize,
                         SMEM_TOTAL);
    fused_kernel<<<GRID, THREADS, SMEM_TOTAL>>>(x, b, out);
}

// round 12
// speedup vs baseline: 1.1608x; 1.0554x over previous
#include <cuda_runtime.h>
#include <cuda_bf16.h>
#include <cstdint>

// ---------------------------------------------------------------------------
//   y   = W @ x + b   (oc=128, cin=128, vox=186624)
//   out = leaky_0.2( y * (y + att[c,l,pp]/nz[c,l] + 1) )
// GEMM on mma.sync m16n8k16 (bf16) via 3-way split: Wh*xh + Wh*xl + Wl*xh
// R12: prep rebuilt (register-retained slab, smem-atomic nz counts, STS.16
//      scatter into 10KB staging, coalesced uint4 copy-out). Fused = R11
//      verbatim (verified 72us).
// ---------------------------------------------------------------------------

#define CIN    128
#define COUT   128
#define HWDIM  5184
#define NVOX   186624
#define PATCH  9
#define PPSQ   81
#define NW     576
#define LPATCH 2304

#define TILE_V  64
#define NT64    2916          // NVOX / 64
#define GRID    296           // 2 CTAs per SM
#define THREADS 256

// per-CTA dynamic smem (bytes):
//   xh 16KB @0, xl 16KB @16384, Wh 32KB @32768, Wl 32KB @65536
#define SM_XH 0
#define SM_XL 16384
#define SM_W  32768
#define SMEM_TOTAL 98304      // 96KB -> 2 CTAs/SM

__device__ __align__(16) unsigned short g_Wsw[32768];        // [Wh][Wl], swizzled
__device__ __align__(16) unsigned short g_atts2[COUT * NVOX]; // bf16 att/nz, voxel-major

// ---------------------------------------------------------------------------
// helpers
// ---------------------------------------------------------------------------
__device__ __forceinline__ uint32_t smem_u32(const void* p) {
    uint32_t a;
    asm("{ .reg .u64 t; cvta.to.shared.u64 t, %1; cvt.u32.u64 %0, t; }"
        : "=r"(a) : "l"(p));
    return a;
}
__device__ __forceinline__ uint32_t pack_bf16x2(float lo, float hi) {
    uint32_t r;
    asm("cvt.rn.bf16x2.f32 %0, %1, %2;" : "=r"(r) : "f"(hi), "f"(lo));
    return r;
}
__device__ __forceinline__ void sts128(uint32_t addr, uint32_t a, uint32_t b,
                                       uint32_t c, uint32_t d) {
    asm volatile("st.shared.v4.u32 [%0], {%1, %2, %3, %4};"
                 :: "r"(addr), "r"(a), "r"(b), "r"(c), "r"(d) : "memory");
}
__device__ __forceinline__ void ldsm_x4(uint32_t addr, uint32_t* r) {
    asm volatile("ldmatrix.sync.aligned.m8n8.x4.shared.b16 {%0,%1,%2,%3}, [%4];"
                 : "=r"(r[0]), "=r"(r[1]), "=r"(r[2]), "=r"(r[3]) : "r"(addr));
}
__device__ __forceinline__ void ldsm_x4_t(uint32_t addr, uint32_t* r) {
    asm volatile("ldmatrix.sync.aligned.m8n8.x4.trans.shared.b16 {%0,%1,%2,%3}, [%4];"
                 : "=r"(r[0]), "=r"(r[1]), "=r"(r[2]), "=r"(r[3]) : "r"(addr));
}
__device__ __forceinline__ void mma16816(float* d, const uint32_t* a,
                                         uint32_t b0, uint32_t b1) {
    asm volatile(
        "mma.sync.aligned.m16n8k16.row.col.f32.bf16.bf16.f32 "
        "{%0,%1,%2,%3}, {%4,%5,%6,%7}, {%8,%9}, {%0,%1,%2,%3};"
        : "+f"(d[0]), "+f"(d[1]), "+f"(d[2]), "+f"(d[3])
        : "r"(a[0]), "r"(a[1]), "r"(a[2]), "r"(a[3]), "r"(b0), "r"(b1));
}
__device__ __forceinline__ uint32_t ldg_u32(const void* p) {
    uint32_t v;
    asm volatile("ld.global.nc.u32 %0, [%1];" : "=r"(v) : "l"(p));
    return v;
}
// W-tile swizzle (256B rows, verified)
__device__ __forceinline__ uint32_t swz(int row, uint32_t colbyte) {
    return (uint32_t)row * 256u + (colbyte ^ (uint32_t)((row & 7) << 4));
}

// ---------------------------------------------------------------------------
// Prep v3: W bf16 hi/lo split (verified) + att -> voxel-major bf16(att/nz).
// CTA = (oc, id, iwb). Register-retained slab, smem-atomic counts, STS.16
// scatter into staging, coalesced uint4 copy-out. Mapping identical to R11:
//   obuf[pd*576 + iw*9 + pw]  ->  g_atts2[oc][ (id*9+pd)*HWDIM + iwb*576 + j ]
// ---------------------------------------------------------------------------
__global__ __launch_bounds__(256) void prep_kernel(const float* __restrict__ att,
                                                   const float* __restrict__ W)
{
    __shared__ unsigned short obuf[9 * 576];   // 10368 B staging
    __shared__ int   scnt[64];
    __shared__ float sinv[64];

    const int tid = threadIdx.x;
    const int blk = blockIdx.x;

    if (blk < 64) {   // W split (verified)
        int idx = blk * 256 + tid;
        int oc = idx >> 7, k = idx & 127;
        float w = W[idx];
        __nv_bfloat16 h = __float2bfloat16(w);
        float hf = __bfloat162float(h);
        __nv_bfloat16 l = __float2bfloat16(w - hf);
        uint32_t off = swz(oc, (uint32_t)(k * 2)) >> 1;
        g_Wsw[off]         = *(unsigned short*)&h;
        g_Wsw[off + 16384] = *(unsigned short*)&l;
    }

    const int oc  = blk / 36;
    const int rem = blk - oc * 36;
    const int id  = rem / 9;
    const int iwb = rem - id * 9;

    if (tid < 64) scnt[tid] = 0;
    __syncthreads();

    // --- phase 0: load slab into registers + count nonzeros per row ---
    const float4* s4 = (const float4*)(att
        + (size_t)(oc * LPATCH + id * 576 + iwb * 64) * PPSQ);
    float4 fr[6];
#pragma unroll
    for (int p = 0; p < 6; p++) {
        int i = tid + 256 * p;
        if (i < 1296) {
            float4 f = __ldg(s4 + i);
            fr[p] = f;
            int e   = i * 4;
            int r0  = e / 81;
            int rm0 = e - r0 * 81;
            float v[4] = { f.x, f.y, f.z, f.w };
            int c0 = 0, c1 = 0;
#pragma unroll
            for (int j = 0; j < 4; j++) {
                int cross = (rm0 + j >= 81);
                int nz = (v[j] != 0.0f);
                c0 += nz & (cross ^ 1);
                c1 += nz & cross;
            }
            atomicAdd(&scnt[r0], c0);
            if (c1) atomicAdd(&scnt[r0 + 1], c1);
        }
    }
    __syncthreads();
    if (tid < 64) sinv[tid] = 1.0f / ((float)scnt[tid] + 1e-5f);
    __syncthreads();

    // --- phase 1: scale + bf16 + scatter into voxel-major staging ---
#pragma unroll
    for (int p = 0; p < 6; p++) {
        int i = tid + 256 * p;
        if (i < 1296) {
            int e   = i * 4;
            int row = e / 81;
            int pp0 = e - row * 81;
            float4 f = fr[p];
            float v[4] = { f.x, f.y, f.z, f.w };
#pragma unroll
            for (int j = 0; j < 4; j++) {
                int ppj = pp0 + j;
                int rj  = row;
                if (ppj >= 81) { ppj -= 81; rj = row + 1; }
                int pd = ppj / 9;
                int pw = ppj - pd * 9;
                __nv_bfloat16 u = __float2bfloat16(v[j] * sinv[rj]);
                obuf[pd * 576 + rj * 9 + pw] = *(unsigned short*)&u;
            }
        }
    }
    __syncthreads();

    // --- phase 2: coalesced copy-out (648 uint4) ---
    {
        const uint4* src = (const uint4*)obuf;
        unsigned short* dstbase = g_atts2
            + (size_t)oc * NVOX + (size_t)(id * 9) * HWDIM + iwb * 576;
        for (int q = tid; q < 648; q += 256) {
            int pd = q / 72;
            int w  = q - pd * 72;
            *(uint4*)(dstbase + (size_t)pd * HWDIM + w * 8) = src[q];
        }
    }
}

// ---------------------------------------------------------------------------
// Fused persistent kernel: CTA = 128 oc x 64 vox, 8 warps (4 oc x 2 vox),
// warp tile 32 oc x 32 vox, single-buffered x, 2 CTAs/SM.  (R11 verbatim)
// ---------------------------------------------------------------------------
struct XFrag { float4 f[8]; };

// thread = 4 k-rows x 8 consecutive vox: k0 = wid*16 + (lane>>3)*4, vox (lane&7)*8
__device__ __forceinline__ void ldg_tile(const float* __restrict__ x,
                                         int v0, int wid, int lane, XFrag& r)
{
    const int k0 = wid * 16 + (lane >> 3) * 4;
    const float* xp = x + (size_t)k0 * NVOX + v0 + (lane & 7) * 8;
#pragma unroll
    for (int i = 0; i < 4; i++) {
        r.f[2 * i]     = *(const float4*)(xp + (size_t)i * NVOX);
        r.f[2 * i + 1] = *(const float4*)(xp + (size_t)i * NVOX + 4);
    }
}

// buffer: 128 k-rows x 64 vox bf16, 128B rows, 16B-chunk xor (k&7); STS.128
__device__ __forceinline__ void sts_tile(uint32_t bufH, int wid, int lane,
                                         const XFrag& r)
{
    const int k0 = wid * 16 + (lane >> 3) * 4;
    const uint32_t voxb = (uint32_t)((lane & 7) * 16);
#pragma unroll
    for (int i = 0; i < 4; i++) {
        const int k = k0 + i;
        float4 fa = r.f[2 * i];
        float4 fb = r.f[2 * i + 1];
        uint32_t h0 = pack_bf16x2(fa.x, fa.y);
        uint32_t h1 = pack_bf16x2(fa.z, fa.w);
        uint32_t h2 = pack_bf16x2(fb.x, fb.y);
        uint32_t h3 = pack_bf16x2(fb.z, fb.w);
        float a0 = __uint_as_float(h0 << 16), a1 = __uint_as_float(h0 & 0xffff0000u);
        float a2 = __uint_as_float(h1 << 16), a3 = __uint_as_float(h1 & 0xffff0000u);
        float a4 = __uint_as_float(h2 << 16), a5 = __uint_as_float(h2 & 0xffff0000u);
        float a6 = __uint_as_float(h3 << 16), a7 = __uint_as_float(h3 & 0xffff0000u);
        uint32_t l0 = pack_bf16x2(fa.x - a0, fa.y - a1);
        uint32_t l1 = pack_bf16x2(fa.z - a2, fa.w - a3);
        uint32_t l2 = pack_bf16x2(fb.x - a4, fb.y - a5);
        uint32_t l3 = pack_bf16x2(fb.z - a6, fb.w - a7);
        uint32_t addr = bufH + (uint32_t)k * 128u
                      + (voxb ^ (uint32_t)((k & 7) << 4));
        sts128(addr,         h0, h1, h2, h3);
        sts128(addr + 16384, l0, l1, l2, l3);   // xl 16KB after xh
    }
}

__global__ __launch_bounds__(THREADS, 2)
void fused_kernel(const float* __restrict__ x,
                  const float* __restrict__ b,
                  float* __restrict__ out)
{
    extern __shared__ __align__(16) char smem[];
    const uint32_t sbase = smem_u32(smem);
    const int tid  = threadIdx.x;
    const int lane = tid & 31;
    const int wid  = tid >> 5;              // 0..7

    // --- load full W once (64KB) ---
    {
        const float4* Wv = (const float4*)g_Wsw;
        float4* sWv = (float4*)(smem + SM_W);
#pragma unroll
        for (int i = 0; i < 16; i++)
            sWv[tid + THREADS * i] = Wv[tid + THREADS * i];
    }

    const int ocb = (wid & 3) * 32;         // oc group (32 oc per warp)
    const int vh  = (wid >> 2) * 32;        // vox group within 64
    const int ocl = ocb + (lane >> 2);

    // A-side ldmatrix ([oc][k] 256B rows, verified)
    const int aRow = ocb + (lane & 15);
    const uint32_t aSw = (uint32_t)((aRow & 7) << 4);
    const uint32_t aK  = (uint32_t)((lane >> 4) * 16);
    const uint32_t aB  = sbase + SM_W + (uint32_t)aRow * 256u;

    // B-side ldmatrix.trans (128B rows, xor (k&7), verified)
    const int bK = lane & 15;
    uint32_t bOff[2];
#pragma unroll
    for (int nbp = 0; nbp < 2; nbp++) {
        uint32_t voxbyte = (uint32_t)(vh * 2 + nbp * 32 + (lane >> 4) * 16);
        bOff[nbp] = (uint32_t)bK * 128u
                  + (voxbyte ^ ((uint32_t)(bK & 7) << 4));
    }

    const float bias0a = __ldg(b + ocl);
    const float bias0b = __ldg(b + ocl + 8);
    const float bias1a = __ldg(b + ocl + 16);
    const float bias1b = __ldg(b + ocl + 24);

    // prologue: tile0 into the single buffer
    int t = blockIdx.x;
    {
        XFrag r0;
        ldg_tile(x, t * TILE_V, wid, lane, r0);
        sts_tile(sbase + SM_XH, wid, lane, r0);
    }
    __syncthreads();

    while (true) {
        const int tn = t + GRID;
        const bool has_next = (tn < NT64);

        // prefetch next x tile into regs (hidden under MMA)
        XFrag rn;
        if (has_next) ldg_tile(x, tn * TILE_V, wid, lane, rn);

        // prefetch epilogue att (voxel-major, coalesced u32 = (v, v+1) pair)
        uint32_t avr[2][2][4];
        {
            const int vb = t * TILE_V + vh + 2 * (lane & 3);
#pragma unroll
            for (int tt = 0; tt < 2; tt++) {
                const unsigned short* A0 =
                    g_atts2 + (size_t)(ocl + 16 * tt) * NVOX + vb;
                const unsigned short* A1 = A0 + (size_t)8 * NVOX;
#pragma unroll
                for (int nb = 0; nb < 4; nb++) {
                    avr[tt][0][nb] = ldg_u32(A0 + nb * 8);
                    avr[tt][1][nb] = ldg_u32(A1 + nb * 8);
                }
            }
        }

        // accumulators, init with bias
        float acc[2][4][4];
#pragma unroll
        for (int nb = 0; nb < 4; nb++) {
            acc[0][nb][0] = bias0a; acc[0][nb][1] = bias0a;
            acc[0][nb][2] = bias0b; acc[0][nb][3] = bias0b;
            acc[1][nb][0] = bias1a; acc[1][nb][1] = bias1a;
            acc[1][nb][2] = bias1b; acc[1][nb][3] = bias1b;
        }

        // MMA over 8 k-steps, 3 split terms (verified inner loop)
        const uint32_t bufH = sbase + SM_XH;
        const uint32_t bufL = sbase + SM_XL;
#pragma unroll
        for (int ks = 0; ks < 8; ks++) {
            const uint32_t kbA = ((uint32_t)(ks * 32) + aK) ^ aSw;
            uint32_t a0h[4], a1h[4], a0l[4], a1l[4];
            ldsm_x4(aB + kbA,                a0h);
            ldsm_x4(aB + 4096 + kbA,         a1h);
            ldsm_x4(aB + 32768 + kbA,        a0l);
            ldsm_x4(aB + 32768 + 4096 + kbA, a1l);

            const uint32_t krow = (uint32_t)(ks * 2048);   // 16 rows x 128B
#pragma unroll
            for (int nbp = 0; nbp < 2; nbp++) {
                uint32_t bh[4], bl[4];
                ldsm_x4_t(bufH + krow + bOff[nbp], bh);
                ldsm_x4_t(bufL + krow + bOff[nbp], bl);
                float* A00 = acc[0][2 * nbp];
                float* A10 = acc[1][2 * nbp];
                float* A01 = acc[0][2 * nbp + 1];
                float* A11 = acc[1][2 * nbp + 1];
                mma16816(A00, a0h, bh[0], bh[1]);
                mma16816(A10, a1h, bh[0], bh[1]);
                mma16816(A01, a0h, bh[2], bh[3]);
                mma16816(A11, a1h, bh[2], bh[3]);
                mma16816(A00, a0h, bl[0], bl[1]);
                mma16816(A10, a1h, bl[0], bl[1]);
                mma16816(A01, a0h, bl[2], bl[3]);
                mma16816(A11, a1h, bl[2], bl[3]);
                mma16816(A00, a0l, bh[0], bh[1]);
                mma16816(A10, a1l, bh[0], bh[1]);
                mma16816(A01, a0l, bh[2], bh[3]);
                mma16816(A11, a1l, bh[2], bh[3]);
            }
        }

        __syncthreads();   // all warps done reading the buffer

        // refill the single buffer with the next tile
        if (has_next) sts_tile(sbase + SM_XH, wid, lane, rn);

        // epilogue: regs + STG only
        const int voxbase = t * TILE_V + vh + 2 * (lane & 3);
#pragma unroll
        for (int tt = 0; tt < 2; tt++) {
            float* o0 = out + (size_t)(ocl + 16 * tt) * NVOX;
            float* o1 = o0 + (size_t)8 * NVOX;
#pragma unroll
            for (int nb = 0; nb < 4; nb++) {
                const int v = voxbase + nb * 8;
                uint32_t u0 = avr[tt][0][nb];
                uint32_t u1 = avr[tt][1][nb];
                float a00 = __uint_as_float(u0 << 16);
                float a01 = __uint_as_float(u0 & 0xffff0000u);
                float a10 = __uint_as_float(u1 << 16);
                float a11 = __uint_as_float(u1 & 0xffff0000u);

                float y;
                float2 r;
                y = acc[tt][nb][0]; r.x = y * (y + a00 + 1.0f);
                r.x = (r.x >= 0.0f) ? r.x : 0.2f * r.x;
                y = acc[tt][nb][1]; r.y = y * (y + a01 + 1.0f);
                r.y = (r.y >= 0.0f) ? r.y : 0.2f * r.y;
                *(float2*)(o0 + v) = r;

                y = acc[tt][nb][2]; r.x = y * (y + a10 + 1.0f);
                r.x = (r.x >= 0.0f) ? r.x : 0.2f * r.x;
                y = acc[tt][nb][3]; r.y = y * (y + a11 + 1.0f);
                r.y = (r.y >= 0.0f) ? r.y : 0.2f * r.y;
                *(float2*)(o1 + v) = r;
            }
        }

        if (!has_next) break;
        __syncthreads();   // buffer ready for next MMA
        t = tn;
    }
}

// ---------------------------------------------------------------------------
extern "C" void kernel_launch(void* const* d_in, const int* in_sizes, int n_in,
                              void* d_out, int out_size)
{
    (void)in_sizes; (void)n_in; (void)out_size;
    const float* x   = (const float*)d_in[0];
    const float* att = (const float*)d_in[1];
    const float* W   = (const float*)d_in[2];
    const float* b   = (const float*)d_in[3];
    float* out = (float*)d_out;

    // 128 oc x 4 id x 9 iw-blocks = 4608 CTAs; first 64 also split W
    prep_kernel<<<4608, 256>>>(att, W);

    cudaFuncSetAttribute(fused_kernel,
                         cudaFuncAttributeMaxDynamicSharedMemorySize,
                         SMEM_TOTAL);
    fused_kernel<<<GRID, THREADS, SMEM_TOTAL>>>(x, b, out);
}

// round 13
// speedup vs baseline: 1.3441x; 1.1579x over previous
#include <cuda_runtime.h>
#include <cuda_bf16.h>
#include <cstdint>

// ---------------------------------------------------------------------------
//   y   = W @ x + b   (oc=128, cin=128, vox=186624)
//   out = leaky_0.2( y * (y + att[c,l,pp]/nz[c,l] + 1) )
// GEMM on mma.sync m16n8k16 (bf16) via 3-way split: Wh*xh + Wh*xl + Wl*xh
// R13: epilogue via smem restage (x buffer reused as [oc][vox] fp32 tile):
//      coalesced att u64 loads + STG.128; prep counting via redux (no atomics).
// ---------------------------------------------------------------------------

#define CIN    128
#define COUT   128
#define HWDIM  5184
#define NVOX   186624
#define PATCH  9
#define PPSQ   81
#define NW     576
#define LPATCH 2304

#define TILE_V  64
#define NT64    2916          // NVOX / 64
#define GRID    296           // 2 CTAs per SM
#define THREADS 256

// per-CTA dynamic smem (bytes):
//   x stage: xh 16KB @0, xl 16KB @16384 (reused as 32KB fp32 out-stage)
//   W: Wh 32KB @32768, Wl 32KB @65536
#define SM_XH 0
#define SM_XL 16384
#define SM_W  32768
#define SMEM_TOTAL 98304      // 96KB -> 2 CTAs/SM

__device__ __align__(16) unsigned short g_Wsw[32768];        // [Wh][Wl], swizzled
__device__ __align__(16) unsigned short g_atts2[COUT * NVOX]; // bf16 att/nz, voxel-major

// ---------------------------------------------------------------------------
// helpers
// ---------------------------------------------------------------------------
__device__ __forceinline__ uint32_t smem_u32(const void* p) {
    uint32_t a;
    asm("{ .reg .u64 t; cvta.to.shared.u64 t, %1; cvt.u32.u64 %0, t; }"
        : "=r"(a) : "l"(p));
    return a;
}
__device__ __forceinline__ uint32_t pack_bf16x2(float lo, float hi) {
    uint32_t r;
    asm("cvt.rn.bf16x2.f32 %0, %1, %2;" : "=r"(r) : "f"(hi), "f"(lo));
    return r;
}
__device__ __forceinline__ int redux_add(int v) {
    int r;
    asm("redux.sync.add.s32 %0, %1, 0xffffffff;" : "=r"(r) : "r"(v));
    return r;
}
__device__ __forceinline__ void sts128(uint32_t addr, uint32_t a, uint32_t b,
                                       uint32_t c, uint32_t d) {
    asm volatile("st.shared.v4.u32 [%0], {%1, %2, %3, %4};"
                 :: "r"(addr), "r"(a), "r"(b), "r"(c), "r"(d) : "memory");
}
__device__ __forceinline__ void sts64f(uint32_t addr, float a, float b) {
    asm volatile("st.shared.v2.f32 [%0], {%1, %2};"
                 :: "r"(addr), "f"(a), "f"(b) : "memory");
}
__device__ __forceinline__ float4 lds128f(uint32_t addr) {
    float4 v;
    asm volatile("ld.shared.v4.f32 {%0,%1,%2,%3}, [%4];"
                 : "=f"(v.x), "=f"(v.y), "=f"(v.z), "=f"(v.w) : "r"(addr));
    return v;
}
__device__ __forceinline__ void ldsm_x4(uint32_t addr, uint32_t* r) {
    asm volatile("ldmatrix.sync.aligned.m8n8.x4.shared.b16 {%0,%1,%2,%3}, [%4];"
                 : "=r"(r[0]), "=r"(r[1]), "=r"(r[2]), "=r"(r[3]) : "r"(addr));
}
__device__ __forceinline__ void ldsm_x4_t(uint32_t addr, uint32_t* r) {
    asm volatile("ldmatrix.sync.aligned.m8n8.x4.trans.shared.b16 {%0,%1,%2,%3}, [%4];"
                 : "=r"(r[0]), "=r"(r[1]), "=r"(r[2]), "=r"(r[3]) : "r"(addr));
}
__device__ __forceinline__ void mma16816(float* d, const uint32_t* a,
                                         uint32_t b0, uint32_t b1) {
    asm volatile(
        "mma.sync.aligned.m16n8k16.row.col.f32.bf16.bf16.f32 "
        "{%0,%1,%2,%3}, {%4,%5,%6,%7}, {%8,%9}, {%0,%1,%2,%3};"
        : "+f"(d[0]), "+f"(d[1]), "+f"(d[2]), "+f"(d[3])
        : "r"(a[0]), "r"(a[1]), "r"(a[2]), "r"(a[3]), "r"(b0), "r"(b1));
}
__device__ __forceinline__ unsigned long long ldg_u64(const void* p) {
    unsigned long long v;
    asm volatile("ld.global.nc.u64 %0, [%1];" : "=l"(v) : "l"(p));
    return v;
}
__device__ __forceinline__ float bf2f(uint32_t v16) {
    return __uint_as_float(v16 << 16);
}
__device__ __forceinline__ float sel4(int r, float a, float b, float c, float d) {
    float v = a;
    v = (r == 1) ? b : v;
    v = (r == 2) ? c : v;
    v = (r == 3) ? d : v;
    return v;
}
__device__ __forceinline__ float leaky_ep(float y, float a) {
    float o = y * (y + a + 1.0f);
    return (o >= 0.0f) ? o : 0.2f * o;
}
// W-tile swizzle (256B rows, verified)
__device__ __forceinline__ uint32_t swz(int row, uint32_t colbyte) {
    return (uint32_t)row * 256u + (colbyte ^ (uint32_t)((row & 7) << 4));
}

// ---------------------------------------------------------------------------
// Prep v4: W split (verified) + att -> voxel-major bf16(att/nz).
// Warp owns 2 groups of 4 rows (register-retained, redux counts — no atomics),
// STS.16 scatter into staging, coalesced uint4 copy-out (verified R12 mapping).
// ---------------------------------------------------------------------------
__device__ __forceinline__ void prep_group(const float4* a4, int g, int lane,
                                           unsigned short* obuf)
{
    float4 f[3];
#pragma unroll
    for (int p = 0; p < 3; p++) {
        int idx = p * 32 + lane;
        if (idx < 81) f[p] = __ldg(a4 + idx);
    }

    // counts per row (verified R7 logic)
    int c0 = 0, c1 = 0, c2 = 0, c3 = 0;
#pragma unroll
    for (int p = 0; p < 3; p++) {
        int idx = p * 32 + lane;
        if (idx < 81) {
            float4 q = f[p];
            int e = idx * 4;
            int r0 = (e >= 81) + (e >= 162) + (e >= 243);
            int r3 = (e + 3 >= 81) + (e + 3 >= 162) + (e + 3 >= 243);
            if (r0 == r3) {
                int cnt = (q.x != 0.f) + (q.y != 0.f) + (q.z != 0.f) + (q.w != 0.f);
                c0 += (r0 == 0) ? cnt : 0;
                c1 += (r0 == 1) ? cnt : 0;
                c2 += (r0 == 2) ? cnt : 0;
                c3 += (r0 == 3) ? cnt : 0;
            } else {
                float vv[4] = { q.x, q.y, q.z, q.w };
#pragma unroll
                for (int j = 0; j < 4; j++) {
                    int ej = e + j;
                    int rj = (ej >= 81) + (ej >= 162) + (ej >= 243);
                    int nz = (vv[j] != 0.f);
                    c0 += (rj == 0) ? nz : 0;
                    c1 += (rj == 1) ? nz : 0;
                    c2 += (rj == 2) ? nz : 0;
                    c3 += (rj == 3) ? nz : 0;
                }
            }
        }
    }
    c0 = redux_add(c0); c1 = redux_add(c1);
    c2 = redux_add(c2); c3 = redux_add(c3);
    float i0 = 1.0f / ((float)c0 + 1e-5f);
    float i1 = 1.0f / ((float)c1 + 1e-5f);
    float i2 = 1.0f / ((float)c2 + 1e-5f);
    float i3 = 1.0f / ((float)c3 + 1e-5f);

    // scale + scatter into voxel-major staging (R12-verified mapping)
#pragma unroll
    for (int p = 0; p < 3; p++) {
        int idx = p * 32 + lane;
        if (idx < 81) {
            float4 q = f[p];
            float vv[4] = { q.x, q.y, q.z, q.w };
            int e = idx * 4;
#pragma unroll
            for (int j = 0; j < 4; j++) {
                int ej = e + j;
                int rj = (ej >= 81) + (ej >= 162) + (ej >= 243);
                int ppj = ej - rj * 81;
                int pd = ppj / 9;
                int pw = ppj - pd * 9;
                int row = g * 4 + rj;
                float s = sel4(rj, i0, i1, i2, i3);
                __nv_bfloat16 u = __float2bfloat16(vv[j] * s);
                obuf[pd * 576 + row * 9 + pw] = *(unsigned short*)&u;
            }
        }
    }
}

__global__ __launch_bounds__(256) void prep_kernel(const float* __restrict__ att,
                                                   const float* __restrict__ W)
{
    __shared__ unsigned short obuf[9 * 576];   // 10368 B staging

    const int tid = threadIdx.x;
    const int blk = blockIdx.x;

    if (blk < 64) {   // W split (verified)
        int idx = blk * 256 + tid;
        int oc = idx >> 7, k = idx & 127;
        float w = W[idx];
        __nv_bfloat16 h = __float2bfloat16(w);
        float hf = __bfloat162float(h);
        __nv_bfloat16 l = __float2bfloat16(w - hf);
        uint32_t off = swz(oc, (uint32_t)(k * 2)) >> 1;
        g_Wsw[off]         = *(unsigned short*)&h;
        g_Wsw[off + 16384] = *(unsigned short*)&l;
    }

    const int oc  = blk / 36;
    const int rem = blk - oc * 36;
    const int id  = rem / 9;
    const int iwb = rem - id * 9;
    const int wid = tid >> 5;
    const int lane = tid & 31;

    // slab base (64 rows x 81 floats = 1296 float4)
    const float4* slab = (const float4*)(att
        + (size_t)(oc * LPATCH + id * 576 + iwb * 64) * PPSQ);

    // warp handles groups 2*wid and 2*wid+1 (4 rows each)
    prep_group(slab + (size_t)(2 * wid) * 81,     2 * wid,     lane, obuf);
    prep_group(slab + (size_t)(2 * wid + 1) * 81, 2 * wid + 1, lane, obuf);
    __syncthreads();

    // coalesced copy-out (648 uint4) — verified R12 mapping
    {
        const uint4* src = (const uint4*)obuf;
        unsigned short* dstbase = g_atts2
            + (size_t)oc * NVOX + (size_t)(id * 9) * HWDIM + iwb * 576;
        for (int q = tid; q < 648; q += 256) {
            int pd = q / 72;
            int w  = q - pd * 72;
            *(uint4*)(dstbase + (size_t)pd * HWDIM + w * 8) = src[q];
        }
    }
}

// ---------------------------------------------------------------------------
// Fused persistent kernel: CTA = 128 oc x 64 vox, 8 warps (4 oc x 2 vox),
// warp tile 32 oc x 32 vox, single-buffered x, 2 CTAs/SM, smem out-restage.
// ---------------------------------------------------------------------------
struct XFrag { float4 f[8]; };

// thread = 4 k-rows x 8 consecutive vox (verified R11)
__device__ __forceinline__ void ldg_tile(const float* __restrict__ x,
                                         int v0, int wid, int lane, XFrag& r)
{
    const int k0 = wid * 16 + (lane >> 3) * 4;
    const float* xp = x + (size_t)k0 * NVOX + v0 + (lane & 7) * 8;
#pragma unroll
    for (int i = 0; i < 4; i++) {
        r.f[2 * i]     = *(const float4*)(xp + (size_t)i * NVOX);
        r.f[2 * i + 1] = *(const float4*)(xp + (size_t)i * NVOX + 4);
    }
}

// buffer: 128 k-rows x 64 vox bf16, 128B rows, 16B-chunk xor (k&7); STS.128 (verified R11)
__device__ __forceinline__ void sts_tile(uint32_t bufH, int wid, int lane,
                                         const XFrag& r)
{
    const int k0 = wid * 16 + (lane >> 3) * 4;
    const uint32_t voxb = (uint32_t)((lane & 7) * 16);
#pragma unroll
    for (int i = 0; i < 4; i++) {
        const int k = k0 + i;
        float4 fa = r.f[2 * i];
        float4 fb = r.f[2 * i + 1];
        uint32_t h0 = pack_bf16x2(fa.x, fa.y);
        uint32_t h1 = pack_bf16x2(fa.z, fa.w);
        uint32_t h2 = pack_bf16x2(fb.x, fb.y);
        uint32_t h3 = pack_bf16x2(fb.z, fb.w);
        float a0 = __uint_as_float(h0 << 16), a1 = __uint_as_float(h0 & 0xffff0000u);
        float a2 = __uint_as_float(h1 << 16), a3 = __uint_as_float(h1 & 0xffff0000u);
        float a4 = __uint_as_float(h2 << 16), a5 = __uint_as_float(h2 & 0xffff0000u);
        float a6 = __uint_as_float(h3 << 16), a7 = __uint_as_float(h3 & 0xffff0000u);
        uint32_t l0 = pack_bf16x2(fa.x - a0, fa.y - a1);
        uint32_t l1 = pack_bf16x2(fa.z - a2, fa.w - a3);
        uint32_t l2 = pack_bf16x2(fb.x - a4, fb.y - a5);
        uint32_t l3 = pack_bf16x2(fb.z - a6, fb.w - a7);
        uint32_t addr = bufH + (uint32_t)k * 128u
                      + (voxb ^ (uint32_t)((k & 7) << 4));
        sts128(addr,         h0, h1, h2, h3);
        sts128(addr + 16384, l0, l1, l2, l3);
    }
}

__global__ __launch_bounds__(THREADS, 2)
void fused_kernel(const float* __restrict__ x,
                  const float* __restrict__ b,
                  float* __restrict__ out)
{
    extern __shared__ __align__(16) char smem[];
    const uint32_t sbase = smem_u32(smem);
    const int tid  = threadIdx.x;
    const int lane = tid & 31;
    const int wid  = tid >> 5;              // 0..7

    // --- load full W once (64KB) ---
    {
        const float4* Wv = (const float4*)g_Wsw;
        float4* sWv = (float4*)(smem + SM_W);
#pragma unroll
        for (int i = 0; i < 16; i++)
            sWv[tid + THREADS * i] = Wv[tid + THREADS * i];
    }

    const int ocb = (wid & 3) * 32;
    const int vh  = (wid >> 2) * 32;
    const int ocl = ocb + (lane >> 2);

    // A-side ldmatrix ([oc][k] 256B rows, verified)
    const int aRow = ocb + (lane & 15);
    const uint32_t aSw = (uint32_t)((aRow & 7) << 4);
    const uint32_t aK  = (uint32_t)((lane >> 4) * 16);
    const uint32_t aB  = sbase + SM_W + (uint32_t)aRow * 256u;

    // B-side ldmatrix.trans (128B rows, xor (k&7), verified)
    const int bK = lane & 15;
    uint32_t bOff[2];
#pragma unroll
    for (int nbp = 0; nbp < 2; nbp++) {
        uint32_t voxbyte = (uint32_t)(vh * 2 + nbp * 32 + (lane >> 4) * 16);
        bOff[nbp] = (uint32_t)bK * 128u
                  + (voxbyte ^ ((uint32_t)(bK & 7) << 4));
    }

    const float bias0a = __ldg(b + ocl);
    const float bias0b = __ldg(b + ocl + 8);
    const float bias1a = __ldg(b + ocl + 16);
    const float bias1b = __ldg(b + ocl + 24);

    // epilogue chunk identity: thread = (row tid>>4 (+16 per it), chunk tid&15)
    const int myrow = tid >> 4;      // 0..15
    const int mych  = tid & 15;      // 16B chunk (4 vox)
    const unsigned short* attp =
        g_atts2 + (size_t)myrow * NVOX + mych * 4;

    // prologue: tile0 into the single buffer
    int t = blockIdx.x;
    {
        XFrag r0;
        ldg_tile(x, t * TILE_V, wid, lane, r0);
        sts_tile(sbase + SM_XH, wid, lane, r0);
    }
    __syncthreads();

    while (true) {
        const int tn = t + GRID;
        const bool has_next = (tn < NT64);

        // prefetch next x tile into regs
        XFrag rn;
        if (has_next) ldg_tile(x, tn * TILE_V, wid, lane, rn);

        // prefetch epilogue att (coalesced u64 = 4 vox of one oc row)
        unsigned long long av[8];
        {
            const unsigned short* ap = attp + (size_t)t * TILE_V;
#pragma unroll
            for (int it = 0; it < 8; it++)
                av[it] = ldg_u64(ap + (size_t)it * 16 * NVOX);
        }

        // accumulators, init with bias
        float acc[2][4][4];
#pragma unroll
        for (int nb = 0; nb < 4; nb++) {
            acc[0][nb][0] = bias0a; acc[0][nb][1] = bias0a;
            acc[0][nb][2] = bias0b; acc[0][nb][3] = bias0b;
            acc[1][nb][0] = bias1a; acc[1][nb][1] = bias1a;
            acc[1][nb][2] = bias1b; acc[1][nb][3] = bias1b;
        }

        // MMA over 8 k-steps, 3 split terms (verified inner loop)
        const uint32_t bufH = sbase + SM_XH;
        const uint32_t bufL = sbase + SM_XL;
#pragma unroll
        for (int ks = 0; ks < 8; ks++) {
            const uint32_t kbA = ((uint32_t)(ks * 32) + aK) ^ aSw;
            uint32_t a0h[4], a1h[4], a0l[4], a1l[4];
            ldsm_x4(aB + kbA,                a0h);
            ldsm_x4(aB + 4096 + kbA,         a1h);
            ldsm_x4(aB + 32768 + kbA,        a0l);
            ldsm_x4(aB + 32768 + 4096 + kbA, a1l);

            const uint32_t krow = (uint32_t)(ks * 2048);
#pragma unroll
            for (int nbp = 0; nbp < 2; nbp++) {
                uint32_t bh[4], bl[4];
                ldsm_x4_t(bufH + krow + bOff[nbp], bh);
                ldsm_x4_t(bufL + krow + bOff[nbp], bl);
                float* A00 = acc[0][2 * nbp];
                float* A10 = acc[1][2 * nbp];
                float* A01 = acc[0][2 * nbp + 1];
                float* A11 = acc[1][2 * nbp + 1];
                mma16816(A00, a0h, bh[0], bh[1]);
                mma16816(A10, a1h, bh[0], bh[1]);
                mma16816(A01, a0h, bh[2], bh[3]);
                mma16816(A11, a1h, bh[2], bh[3]);
                mma16816(A00, a0h, bl[0], bl[1]);
                mma16816(A10, a1h, bl[0], bl[1]);
                mma16816(A01, a0h, bl[2], bl[3]);
                mma16816(A11, a1h, bl[2], bl[3]);
                mma16816(A00, a0l, bh[0], bh[1]);
                mma16816(A10, a1l, bh[0], bh[1]);
                mma16816(A01, a0l, bh[2], bh[3]);
                mma16816(A11, a1l, bh[2], bh[3]);
            }
        }

        __syncthreads();   // MMA done: x buffer is free

        // stage acc -> smem [oc][vox] fp32, row-XOR swizzle (conflict-free)
#pragma unroll
        for (int tt = 0; tt < 2; tt++) {
            int row0 = ocb + (lane >> 2) + 16 * tt;
            int row1 = row0 + 8;
            uint32_t x0 = (uint32_t)((row0 & 7) << 5);
#pragma unroll
            for (int nb = 0; nb < 4; nb++) {
                uint32_t vb4 = (uint32_t)((vh + 2 * (lane & 3) + 8 * nb) * 4);
                sts64f(sbase + (uint32_t)row0 * 256u + (vb4 ^ x0),
                       acc[tt][nb][0], acc[tt][nb][1]);
                sts64f(sbase + (uint32_t)row1 * 256u + (vb4 ^ x0),
                       acc[tt][nb][2], acc[tt][nb][3]);
            }
        }
        __syncthreads();   // staging visible

        // epilogue: coalesced LDS.128 + att regs + STG.128
        {
            float* ob = out + (size_t)myrow * NVOX + t * TILE_V + mych * 4;
#pragma unroll
            for (int it = 0; it < 8; it++) {
                int row = myrow + it * 16;
                float4 y = lds128f(sbase + (uint32_t)row * 256u
                                   + ((uint32_t)(mych * 16)
                                      ^ (uint32_t)((row & 7) << 5)));
                uint32_t lo = (uint32_t)av[it];
                uint32_t hi = (uint32_t)(av[it] >> 32);
                float4 o;
                o.x = leaky_ep(y.x, bf2f(lo & 0xffffu));
                o.y = leaky_ep(y.y, bf2f(lo >> 16));
                o.z = leaky_ep(y.z, bf2f(hi & 0xffffu));
                o.w = leaky_ep(y.w, bf2f(hi >> 16));
                *(float4*)(ob + (size_t)it * 16 * NVOX) = o;
            }
        }
        __syncthreads();   // staging reads done: buffer free for refill

        if (has_next) {
            sts_tile(sbase + SM_XH, wid, lane, rn);
            __syncthreads();   // buffer ready
            t = tn;
        } else {
            break;
        }
    }
}

// ---------------------------------------------------------------------------
extern "C" void kernel_launch(void* const* d_in, const int* in_sizes, int n_in,
                              void* d_out, int out_size)
{
    (void)in_sizes; (void)n_in; (void)out_size;
    const float* x   = (const float*)d_in[0];
    const float* att = (const float*)d_in[1];
    const float* W   = (const float*)d_in[2];
    const float* b   = (const float*)d_in[3];
    float* out = (float*)d_out;

    // 128 oc x 4 id x 9 iw-blocks = 4608 CTAs; first 64 also split W
    prep_kernel<<<4608, 256>>>(att, W);

    cudaFuncSetAttribute(fused_kernel,
                         cudaFuncAttributeMaxDynamicSharedMemorySize,
                         SMEM_TOTAL);
    fused_kernel<<<GRID, THREADS, SMEM_TOTAL>>>(x, b, out);
}